// round 12
// baseline (speedup 1.0000x reference)
#include <cuda_runtime.h>
#include <cuda_bf16.h>
#include <math.h>

// Problem constants (fixed by the dataset)
#define MAX_NODES 50000
#define MAX_ENV   1000000
#define DHID1 32
#define DHID2 64
#define DIN   9
#define NAXIS 8
#define NDESC (DHID2 * NAXIS)   // 512

typedef unsigned long long ull_t;

// Scratch: per-env MLP outputs h3 [env][64], and the destination-node binning
__device__ __align__(16) float g_h[(size_t)MAX_ENV * DHID2];       // 256 MB
__device__ int g_count[MAX_NODES];
__device__ int g_start[MAX_NODES];
__device__ int g_cursor[MAX_NODES];
__device__ int g_order[MAX_ENV];

// Dynamic shared-memory partition (float offsets)
#define OFF_W1   0
#define OFF_B1   288
#define OFF_W2   320
#define OFF_B2   2368
#define OFF_W3   2432
#define OFF_B3   6528
#define OFF_H    6592               // 4 warps * 64*32
#define SMEM_FLOATS (OFF_H + 4*2048)
#define SMEM_BYTES  (SMEM_FLOATS * 4)

// ---------------------------------------------------------------------------
// helpers
// ---------------------------------------------------------------------------
__device__ __forceinline__ float fast_tanh(float x) {
    // 5-op clamp-free tanh: 1 - 2/(e^{2x}+1). e=inf -> 1, e=0 -> -1. ~1e-6 rel.
    float e = __expf(2.0f * x);
    float rcp;
    asm("rcp.approx.f32 %0, %1;" : "=f"(rcp) : "f"(e + 1.0f));
    return fmaf(-2.0f, rcp, 1.0f);
}

__device__ __forceinline__ ull_t pack2(float x) {
    ull_t r;
    asm("mov.b64 %0, {%1, %1};" : "=l"(r) : "f"(x));
    return r;
}
__device__ __forceinline__ void fma2(ull_t& acc, ull_t a, ull_t b) {
    asm("fma.rn.f32x2 %0, %1, %2, %0;" : "+l"(acc) : "l"(a), "l"(b));
}
__device__ __forceinline__ float2 unpack2(ull_t v) {
    float2 f;
    asm("mov.b64 {%0, %1}, %2;" : "=f"(f.x), "=f"(f.y) : "l"(v));
    return f;
}

// ---------------------------------------------------------------------------
// binning kernels
// ---------------------------------------------------------------------------
__global__ void zero_count_kernel(int* cnt, int n) {
    int i = blockIdx.x * blockDim.x + threadIdx.x;
    if (i < n) cnt[i] = 0;
}

__global__ void hist_kernel(const int* __restrict__ env_index, int n_env,
                            int* __restrict__ cnt) {
    int i = blockIdx.x * blockDim.x + threadIdx.x;
    if (i < n_env) atomicAdd(&cnt[env_index[n_env + i]], 1);
}

// single-block exclusive scan of counts -> start & cursor (shfl warp scan)
__global__ __launch_bounds__(1024)
void scan_kernel(const int* __restrict__ cnt, int* __restrict__ start,
                 int* __restrict__ cursor, int n_nodes) {
    __shared__ int swarp[32];
    int t = threadIdx.x;
    int lane = t & 31;
    int w = t >> 5;
    int carry = 0;
    for (int base = 0; base < n_nodes; base += 1024) {
        int idx = base + t;
        int v = (idx < n_nodes) ? cnt[idx] : 0;
        // warp inclusive scan
        int incl = v;
        #pragma unroll
        for (int off = 1; off < 32; off <<= 1) {
            int u = __shfl_up_sync(0xFFFFFFFF, incl, off);
            if (lane >= off) incl += u;
        }
        if (lane == 31) swarp[w] = incl;
        __syncthreads();
        if (w == 0) {
            int s = swarp[lane];
            #pragma unroll
            for (int off = 1; off < 32; off <<= 1) {
                int u = __shfl_up_sync(0xFFFFFFFF, s, off);
                if (lane >= off) s += u;
            }
            swarp[lane] = s;   // inclusive scan of warp sums
        }
        __syncthreads();
        int warp_off = (w > 0) ? swarp[w - 1] : 0;
        int excl = carry + warp_off + incl - v;
        if (idx < n_nodes) { start[idx] = excl; cursor[idx] = excl; }
        carry += swarp[31];
        __syncthreads();
    }
}

__global__ void scatter_kernel(const int* __restrict__ env_index, int n_env,
                               int* __restrict__ cursor, int* __restrict__ order) {
    int i = blockIdx.x * blockDim.x + threadIdx.x;
    if (i < n_env) {
        int d = env_index[n_env + i];
        int p = atomicAdd(&cursor[d], 1);
        order[p] = i;
    }
}

// ---------------------------------------------------------------------------
// Phase A: per-env MLP (no atomics). Layers 1-2 per-thread (packed FFMA2);
// layer 3 warp-cooperative 32env x 64out tile over smem-staged h2.
// Epilogue streams h3 rows to g_h.
// ---------------------------------------------------------------------------
__global__ __launch_bounds__(128)
void env_mlp_store(const float* __restrict__ env_vec,
                   const float* __restrict__ atom_attr,
                   const int*   __restrict__ env_index,
                   const float* __restrict__ W1, const float* __restrict__ B1,
                   const float* __restrict__ W2, const float* __restrict__ B2,
                   const float* __restrict__ W3, const float* __restrict__ B3,
                   int n_env)
{
    extern __shared__ __align__(16) float sm[];
    float* sW1 = sm + OFF_W1;
    float* sB1 = sm + OFF_B1;
    float* sW2 = sm + OFF_W2;
    float* sB2 = sm + OFF_B2;
    float* sW3 = sm + OFF_W3;
    float* sB3 = sm + OFF_B3;

    for (int i = threadIdx.x; i < DIN * DHID1;   i += blockDim.x) sW1[i] = W1[i];
    for (int i = threadIdx.x; i < DHID1 * DHID2; i += blockDim.x) sW2[i] = W2[i];
    for (int i = threadIdx.x; i < DHID2 * DHID2; i += blockDim.x) sW3[i] = W3[i];
    if (threadIdx.x < DHID1) sB1[threadIdx.x] = B1[threadIdx.x];
    if (threadIdx.x < DHID2) { sB2[threadIdx.x] = B2[threadIdx.x]; sB3[threadIdx.x] = B3[threadIdx.x]; }
    __syncthreads();

    int warp = threadIdx.x >> 5;
    int lane = threadIdx.x & 31;
    float* sHw = sm + OFF_H + warp * 2048;          // [64 k][32 env]

    int warp_env_base = (blockIdx.x * 4 + warp) * 32;
    int e_mine = warp_env_base + lane;
    int e = min(e_mine, n_env - 1);

    // ---- per-env input ----
    float vx = env_vec[3 * e + 0];
    float vy = env_vec[3 * e + 1];
    float vz = env_vec[3 * e + 2];
    float r  = sqrtf(vx * vx + vy * vy + vz * vz);

    float snorm;
    if (r < 3.0f) {
        snorm = 1.0f / r;
    } else if (r < 6.0f) {
        float x = (r - 6.0f) * (-1.0f / 3.0f);
        snorm = (1.0f / r) * (x * x * x * (10.0f + x * (-15.0f + 6.0f * x)) + 1.0f);
    } else {
        snorm = 0.0f;
    }

    int src = env_index[e];
    int dst = env_index[n_env + e];
    float4 as = *(const float4*)(atom_attr + 4 * src);
    float4 ad = *(const float4*)(atom_attr + 4 * dst);
    float in[DIN] = {snorm, as.x, as.y, as.z, as.w, ad.x, ad.y, ad.z, ad.w};

    // ---- layer 1: [9] -> [32] ----
    float h1[DHID1];
    {
        ull_t acc[16];
        #pragma unroll
        for (int j = 0; j < 16; j++) acc[j] = *(const ull_t*)(sB1 + 2 * j);
        #pragma unroll
        for (int k = 0; k < DIN; k++) {
            ull_t x2 = pack2(in[k]);
            #pragma unroll
            for (int jj = 0; jj < 8; jj++) {
                ulonglong2 w = *(const ulonglong2*)(sW1 + k * DHID1 + jj * 4);
                fma2(acc[2 * jj + 0], x2, w.x);
                fma2(acc[2 * jj + 1], x2, w.y);
            }
        }
        #pragma unroll
        for (int j = 0; j < 16; j++) {
            float2 t = unpack2(acc[j]);
            h1[2 * j + 0] = fast_tanh(t.x);
            h1[2 * j + 1] = fast_tanh(t.y);
        }
    }

    // ---- layer 2: [32] -> [64], j-chunks of 32; stage h2 straight to smem ----
    #pragma unroll
    for (int c = 0; c < DHID2; c += 32) {
        ull_t acc[16];
        #pragma unroll
        for (int j = 0; j < 16; j++) acc[j] = *(const ull_t*)(sB2 + c + 2 * j);
        #pragma unroll
        for (int k = 0; k < DHID1; k++) {
            ull_t x2 = pack2(h1[k]);
            #pragma unroll
            for (int jj = 0; jj < 8; jj++) {
                ulonglong2 w = *(const ulonglong2*)(sW2 + k * DHID2 + c + jj * 4);
                fma2(acc[2 * jj + 0], x2, w.x);
                fma2(acc[2 * jj + 1], x2, w.y);
            }
        }
        #pragma unroll
        for (int j = 0; j < 16; j++) {
            float2 t = unpack2(acc[j]);
            sHw[(c + 2 * j + 0) * 32 + lane] = fast_tanh(t.x);
            sHw[(c + 2 * j + 1) * 32 + lane] = fast_tanh(t.y);
        }
    }
    __syncwarp();

    // ---- layer 3: warp-tiled. lane = eg*8 + og: envs [8eg,8eg+8), outs [8og,8og+8) ----
    int eg = lane >> 3;
    int og = lane & 7;
    int j0 = og * 8;
    int ebase = eg * 8;

    ull_t acc[8][4];   // [out j][env pair]
    #pragma unroll
    for (int j = 0; j < 8; j++) {
        ull_t b = pack2(sB3[j0 + j]);
        acc[j][0] = b; acc[j][1] = b; acc[j][2] = b; acc[j][3] = b;
    }

    #pragma unroll 8
    for (int k = 0; k < DHID2; k++) {
        ulonglong2 A0 = *(const ulonglong2*)(sHw + k * 32 + ebase);      // envs 0..3
        ulonglong2 A1 = *(const ulonglong2*)(sHw + k * 32 + ebase + 4);  // envs 4..7
        float4 w0 = *(const float4*)(sW3 + k * DHID2 + j0);
        float4 w1 = *(const float4*)(sW3 + k * DHID2 + j0 + 4);
        ull_t wj[8] = {pack2(w0.x), pack2(w0.y), pack2(w0.z), pack2(w0.w),
                       pack2(w1.x), pack2(w1.y), pack2(w1.z), pack2(w1.w)};
        #pragma unroll
        for (int j = 0; j < 8; j++) {
            fma2(acc[j][0], A0.x, wj[j]);
            fma2(acc[j][1], A0.y, wj[j]);
            fma2(acc[j][2], A1.x, wj[j]);
            fma2(acc[j][3], A1.y, wj[j]);
        }
    }

    // epilogue: tanh + residual (h2 read back from smem), stream to g_h
    #pragma unroll
    for (int ep = 0; ep < 4; ep++) {
        int ee0 = ebase + 2 * ep;
        int ee1 = ee0 + 1;
        float v0[8], v1[8];
        #pragma unroll
        for (int j = 0; j < 8; j++) {
            float2 f = unpack2(acc[j][ep]);
            float r0 = sHw[(j0 + j) * 32 + ee0];
            float r1 = sHw[(j0 + j) * 32 + ee1];
            v0[j] = fast_tanh(f.x) + r0;
            v1[j] = fast_tanh(f.y) + r1;
        }
        if (warp_env_base + ee0 < n_env) {
            float* p = g_h + (long)(warp_env_base + ee0) * DHID2 + j0;
            *(float4*)(p + 0) = make_float4(v0[0], v0[1], v0[2], v0[3]);
            *(float4*)(p + 4) = make_float4(v0[4], v0[5], v0[6], v0[7]);
        }
        if (warp_env_base + ee1 < n_env) {
            float* p = g_h + (long)(warp_env_base + ee1) * DHID2 + j0;
            *(float4*)(p + 0) = make_float4(v1[0], v1[1], v1[2], v1[3]);
            *(float4*)(p + 4) = make_float4(v1[4], v1[5], v1[6], v1[7]);
        }
    }
}

// ---------------------------------------------------------------------------
// Phase B: gather-side aggregation (mean of h3*v over bin) + self outer
// product -> node_desc. 4 nodes per 256-thread block; thread owns one d.
// ---------------------------------------------------------------------------
__global__ __launch_bounds__(256)
void agg_node_desc(const int* __restrict__ order,
                   const int* __restrict__ startv,
                   const int* __restrict__ countv,
                   const float* __restrict__ env_vec,
                   float* __restrict__ node_desc, int n_nodes)
{
    __shared__ float sa[4 * 192];
    int local = threadIdx.x >> 6;
    int d     = threadIdx.x & 63;
    int node  = blockIdx.x * 4 + local;

    float a0 = 0.f, a1 = 0.f, a2 = 0.f;
    if (node < n_nodes) {
        int start = startv[node];
        int cnt   = countv[node];
        int e_next = (cnt > 0) ? order[start] : 0;
        for (int i = 0; i < cnt; i++) {
            int e = e_next;
            if (i + 1 < cnt) e_next = order[start + i + 1];
            float h  = g_h[(long)e * DHID2 + d];
            float vx = env_vec[3 * e + 0];
            float vy = env_vec[3 * e + 1];
            float vz = env_vec[3 * e + 2];
            a0 = fmaf(h, vx, a0);
            a1 = fmaf(h, vy, a1);
            a2 = fmaf(h, vz, a2);
        }
        float inv = 1.0f / fmaxf((float)cnt, 1.0f);
        a0 *= inv; a1 *= inv; a2 *= inv;
    }
    sa[local * 192 + 0 * 64 + d] = a0;
    sa[local * 192 + 1 * 64 + d] = a1;
    sa[local * 192 + 2 * 64 + d] = a2;
    __syncthreads();
    if (node >= n_nodes) return;

    const float* a = sa + local * 192;
    float o[NAXIS];
    #pragma unroll
    for (int e2 = 0; e2 < NAXIS; e2++) {
        o[e2] = a0 * a[0 * 64 + e2] + a1 * a[1 * 64 + e2] + a2 * a[2 * 64 + e2];
    }
    float4* dst = (float4*)(node_desc + (long)node * NDESC + d * NAXIS);
    dst[0] = make_float4(o[0], o[1], o[2], o[3]);
    dst[1] = make_float4(o[4], o[5], o[6], o[7]);
}

// ---------------------------------------------------------------------------
// Phase C: edge_desc[e] = node_desc[src] + node_desc[dst]
// ---------------------------------------------------------------------------
__global__ __launch_bounds__(256)
void edge_desc_kernel(const int* __restrict__ edge_index,
                      const float* __restrict__ node_desc,
                      float* __restrict__ edge_desc,
                      int n_edges)
{
    int t = threadIdx.x;
    int eidx = blockIdx.x * 2 + (t >> 7);
    if (eidx >= n_edges) return;
    int j = t & 127;

    int s = edge_index[eidx];
    int d = edge_index[n_edges + eidx];

    float4 x = ((const float4*)(node_desc + (long)s * NDESC))[j];
    float4 y = ((const float4*)(node_desc + (long)d * NDESC))[j];
    float4 rr = make_float4(x.x + y.x, x.y + y.y, x.z + y.z, x.w + y.w);
    __stcs((float4*)(edge_desc + (long)eidx * NDESC) + j, rr);
}

// ---------------------------------------------------------------------------
// launch
// ---------------------------------------------------------------------------
extern "C" void kernel_launch(void* const* d_in, const int* in_sizes, int n_in,
                              void* d_out, int out_size)
{
    const float* env_vec   = (const float*)d_in[0];
    const float* atom_attr = (const float*)d_in[1];
    const int*   env_index = (const int*)  d_in[2];
    const int*   edge_index= (const int*)  d_in[3];
    const float* W1 = (const float*)d_in[4];
    const float* B1 = (const float*)d_in[5];
    const float* W2 = (const float*)d_in[6];
    const float* B2 = (const float*)d_in[7];
    const float* W3 = (const float*)d_in[8];
    const float* B3 = (const float*)d_in[9];

    int n_env   = in_sizes[0] / 3;
    int n_nodes = in_sizes[1] / 4;
    int n_edges = in_sizes[3] / 2;

    float* node_desc = (float*)d_out;
    float* edge_desc = (float*)d_out + (long)n_nodes * NDESC;

    int *cnt_ptr = nullptr, *start_ptr = nullptr, *cursor_ptr = nullptr, *order_ptr = nullptr;
    cudaGetSymbolAddress((void**)&cnt_ptr, g_count);
    cudaGetSymbolAddress((void**)&start_ptr, g_start);
    cudaGetSymbolAddress((void**)&cursor_ptr, g_cursor);
    cudaGetSymbolAddress((void**)&order_ptr, g_order);

    static int smem_set = 0;
    if (!smem_set) {
        cudaFuncSetAttribute(env_mlp_store,
                             cudaFuncAttributeMaxDynamicSharedMemorySize, SMEM_BYTES);
        smem_set = 1;
    }

    // 1. bin env -> destination node
    zero_count_kernel<<<(n_nodes + 255) / 256, 256>>>(cnt_ptr, n_nodes);
    hist_kernel<<<(n_env + 255) / 256, 256>>>(env_index, n_env, cnt_ptr);
    scan_kernel<<<1, 1024>>>(cnt_ptr, start_ptr, cursor_ptr, n_nodes);
    scatter_kernel<<<(n_env + 255) / 256, 256>>>(env_index, n_env, cursor_ptr, order_ptr);

    // 2. per-env MLP, streaming h3 to g_h (no atomics)
    int blocks = (n_env + 127) / 128;
    env_mlp_store<<<blocks, 128, SMEM_BYTES>>>(
        env_vec, atom_attr, env_index, W1, B1, W2, B2, W3, B3, n_env);

    // 3. gather aggregation + node descriptors
    agg_node_desc<<<(n_nodes + 3) / 4, 256>>>(
        order_ptr, start_ptr, cnt_ptr, env_vec, node_desc, n_nodes);

    // 4. edge descriptors
    edge_desc_kernel<<<(n_edges + 1) / 2, 256>>>(edge_index, node_desc, edge_desc, n_edges);
}

// round 14
// speedup vs baseline: 1.1599x; 1.1599x over previous
#include <cuda_runtime.h>
#include <cuda_bf16.h>
#include <math.h>

// Problem constants (fixed by the dataset)
#define MAX_NODES 50000
#define DHID1 32
#define DHID2 64
#define DIN   9
#define NAXIS 8
#define NDESC (DHID2 * NAXIS)   // 512

typedef unsigned long long ull_t;

// Scratch: segment-sum accumulator, axis-major: [node][axis(3)][64]
__device__ __align__(16) float g_sum[(size_t)MAX_NODES * 192];
__device__ float g_cnt[MAX_NODES];

// Dynamic shared-memory partition (float offsets), 8 warps per block
#define NWARP    8
#define OFF_W1   0
#define OFF_B1   288
#define OFF_W2   320
#define OFF_B2   2368
#define OFF_W3   2432
#define OFF_B3   6528
#define OFF_H    6592                       // NWARP * 64*32
#define OFF_V    (OFF_H + NWARP*2048)       // NWARP * 3*32
#define OFF_D    (OFF_V + NWARP*96)         // NWARP * 32 ints
#define SMEM_FLOATS (OFF_D + NWARP*32)
#define SMEM_BYTES  (SMEM_FLOATS * 4)       // 96 KB -> 2 blocks/SM

// ---------------------------------------------------------------------------
// helpers
// ---------------------------------------------------------------------------
__device__ __forceinline__ float fast_tanh(float x) {
    // accurate (~1e-6 rel) tanh: EX2 + RCP path, clamp avoids overflow
    float xc = fminf(fmaxf(x, -9.0f), 9.0f);
    float e  = __expf(2.0f * xc);
    return __fdividef(e - 1.0f, e + 1.0f);
}

__device__ __forceinline__ void red_add_v4(float* p, float a, float b, float c, float d) {
    asm volatile("red.global.add.v4.f32 [%0], {%1, %2, %3, %4};"
                 :: "l"(p), "f"(a), "f"(b), "f"(c), "f"(d) : "memory");
}

__device__ __forceinline__ ull_t pack2(float x) {
    ull_t r;
    asm("mov.b64 %0, {%1, %1};" : "=l"(r) : "f"(x));
    return r;
}
__device__ __forceinline__ void fma2(ull_t& acc, ull_t a, ull_t b) {
    asm("fma.rn.f32x2 %0, %1, %2, %0;" : "+l"(acc) : "l"(a), "l"(b));
}
__device__ __forceinline__ float2 unpack2(ull_t v) {
    float2 f;
    asm("mov.b64 {%0, %1}, %2;" : "=f"(f.x), "=f"(f.y) : "l"(v));
    return f;
}

// ---------------------------------------------------------------------------
// zero scratch
// ---------------------------------------------------------------------------
__global__ void zero_all_kernel(float4* sum4, long n4, float4* cnt4, long c4) {
    long i = (long)blockIdx.x * blockDim.x + threadIdx.x;
    long stride = (long)gridDim.x * blockDim.x;
    float4 z = make_float4(0.f, 0.f, 0.f, 0.f);
    for (long k = i; k < n4; k += stride) sum4[k] = z;
    for (long k = i; k < c4; k += stride) cnt4[k] = z;
}

// ---------------------------------------------------------------------------
// Phase A: per-env MLP. Layers 1-2 per-thread (packed FFMA2); layer 3 as a
// warp-cooperative 32env x 64out GEMM tile over smem-staged h2.
// 256-thread blocks (8 warps share one weight copy) -> 2 blocks/SM,
// 16 warps/SM. Epilogue reads residuals from smem per-chunk to stay <=128 regs.
// ---------------------------------------------------------------------------
__global__ __launch_bounds__(256, 2)
void env_mlp_scatter(const float* __restrict__ env_vec,
                     const float* __restrict__ atom_attr,
                     const int*   __restrict__ env_index,
                     const float* __restrict__ W1, const float* __restrict__ B1,
                     const float* __restrict__ W2, const float* __restrict__ B2,
                     const float* __restrict__ W3, const float* __restrict__ B3,
                     int n_env)
{
    extern __shared__ __align__(16) float sm[];
    float* sW1 = sm + OFF_W1;
    float* sB1 = sm + OFF_B1;
    float* sW2 = sm + OFF_W2;
    float* sB2 = sm + OFF_B2;
    float* sW3 = sm + OFF_W3;
    float* sB3 = sm + OFF_B3;

    for (int i = threadIdx.x; i < DIN * DHID1;   i += blockDim.x) sW1[i] = W1[i];
    for (int i = threadIdx.x; i < DHID1 * DHID2; i += blockDim.x) sW2[i] = W2[i];
    for (int i = threadIdx.x; i < DHID2 * DHID2; i += blockDim.x) sW3[i] = W3[i];
    if (threadIdx.x < DHID1) sB1[threadIdx.x] = B1[threadIdx.x];
    if (threadIdx.x < DHID2) { sB2[threadIdx.x] = B2[threadIdx.x]; sB3[threadIdx.x] = B3[threadIdx.x]; }
    __syncthreads();

    int warp = threadIdx.x >> 5;
    int lane = threadIdx.x & 31;
    float* sHw = sm + OFF_H + warp * 2048;          // [64 k][32 env]
    float* sVw = sm + OFF_V + warp * 96;            // [3][32]
    int*   sDw = (int*)(sm + OFF_D) + warp * 32;    // [32]

    int warp_env_base = (blockIdx.x * NWARP + warp) * 32;
    int e_mine = warp_env_base + lane;
    int e = min(e_mine, n_env - 1);

    // ---- per-env input ----
    float vx = env_vec[3 * e + 0];
    float vy = env_vec[3 * e + 1];
    float vz = env_vec[3 * e + 2];
    float r  = sqrtf(vx * vx + vy * vy + vz * vz);

    float snorm;
    if (r < 3.0f) {
        snorm = 1.0f / r;
    } else if (r < 6.0f) {
        float x = (r - 6.0f) * (-1.0f / 3.0f);
        snorm = (1.0f / r) * (x * x * x * (10.0f + x * (-15.0f + 6.0f * x)) + 1.0f);
    } else {
        snorm = 0.0f;
    }

    int src = env_index[e];
    int dst = env_index[n_env + e];
    float4 as = *(const float4*)(atom_attr + 4 * src);
    float4 ad = *(const float4*)(atom_attr + 4 * dst);
    float in[DIN] = {snorm, as.x, as.y, as.z, as.w, ad.x, ad.y, ad.z, ad.w};

    // ---- layer 1: [9] -> [32] ----
    float h1[DHID1];
    {
        ull_t acc[16];
        #pragma unroll
        for (int j = 0; j < 16; j++) acc[j] = *(const ull_t*)(sB1 + 2 * j);
        #pragma unroll
        for (int k = 0; k < DIN; k++) {
            ull_t x2 = pack2(in[k]);
            #pragma unroll
            for (int jj = 0; jj < 8; jj++) {
                ulonglong2 w = *(const ulonglong2*)(sW1 + k * DHID1 + jj * 4);
                fma2(acc[2 * jj + 0], x2, w.x);
                fma2(acc[2 * jj + 1], x2, w.y);
            }
        }
        #pragma unroll
        for (int j = 0; j < 16; j++) {
            float2 t = unpack2(acc[j]);
            h1[2 * j + 0] = fast_tanh(t.x);
            h1[2 * j + 1] = fast_tanh(t.y);
        }
    }

    // ---- layer 2: [32] -> [64], j-chunks of 32; stage h2 straight to smem ----
    #pragma unroll
    for (int c = 0; c < DHID2; c += 32) {
        ull_t acc[16];
        #pragma unroll
        for (int j = 0; j < 16; j++) acc[j] = *(const ull_t*)(sB2 + c + 2 * j);
        #pragma unroll
        for (int k = 0; k < DHID1; k++) {
            ull_t x2 = pack2(h1[k]);
            #pragma unroll
            for (int jj = 0; jj < 8; jj++) {
                ulonglong2 w = *(const ulonglong2*)(sW2 + k * DHID2 + c + jj * 4);
                fma2(acc[2 * jj + 0], x2, w.x);
                fma2(acc[2 * jj + 1], x2, w.y);
            }
        }
        #pragma unroll
        for (int j = 0; j < 16; j++) {
            float2 t = unpack2(acc[j]);
            sHw[(c + 2 * j + 0) * 32 + lane] = fast_tanh(t.x);
            sHw[(c + 2 * j + 1) * 32 + lane] = fast_tanh(t.y);
        }
    }

    // stage v / dst; per-env count
    sVw[0 * 32 + lane] = vx;
    sVw[1 * 32 + lane] = vy;
    sVw[2 * 32 + lane] = vz;
    sDw[lane] = dst;
    if (e_mine < n_env) atomicAdd(g_cnt + dst, 1.0f);
    __syncwarp();

    // ---- layer 3: warp-tiled. lane = eg*8 + og: envs [8eg,8eg+8), outs [8og,8og+8) ----
    int eg = lane >> 3;
    int og = lane & 7;
    int j0 = og * 8;
    int ebase = eg * 8;

    ull_t acc[8][4];   // [out j][env pair]
    #pragma unroll
    for (int j = 0; j < 8; j++) {
        ull_t b = pack2(sB3[j0 + j]);
        acc[j][0] = b; acc[j][1] = b; acc[j][2] = b; acc[j][3] = b;
    }

    #pragma unroll 8
    for (int k = 0; k < DHID2; k++) {
        ulonglong2 A0 = *(const ulonglong2*)(sHw + k * 32 + ebase);      // envs 0..3
        ulonglong2 A1 = *(const ulonglong2*)(sHw + k * 32 + ebase + 4);  // envs 4..7
        float4 w0 = *(const float4*)(sW3 + k * DHID2 + j0);
        float4 w1 = *(const float4*)(sW3 + k * DHID2 + j0 + 4);
        ull_t wj[8] = {pack2(w0.x), pack2(w0.y), pack2(w0.z), pack2(w0.w),
                       pack2(w1.x), pack2(w1.y), pack2(w1.z), pack2(w1.w)};
        #pragma unroll
        for (int j = 0; j < 8; j++) {
            fma2(acc[j][0], A0.x, wj[j]);
            fma2(acc[j][1], A0.y, wj[j]);
            fma2(acc[j][2], A1.x, wj[j]);
            fma2(acc[j][3], A1.y, wj[j]);
        }
    }

    // epilogue: tanh + residual (read back from smem per chunk), scatter (RED v4)
    #pragma unroll
    for (int ep = 0; ep < 4; ep++) {
        int ee0 = ebase + 2 * ep;
        int ee1 = ee0 + 1;
        float v0[8], v1[8];
        #pragma unroll
        for (int j = 0; j < 8; j++) {
            float2 f = unpack2(acc[j][ep]);
            float r0 = sHw[(j0 + j) * 32 + ee0];
            float r1 = sHw[(j0 + j) * 32 + ee1];
            v0[j] = fast_tanh(f.x) + r0;
            v1[j] = fast_tanh(f.y) + r1;
        }
        #pragma unroll
        for (int half = 0; half < 2; half++) {
            int ee = ebase + 2 * ep + half;
            if (warp_env_base + ee < n_env) {
                const float* vv = half ? v1 : v0;
                float* base = g_sum + (long)sDw[ee] * 192;
                float ax = sVw[0 * 32 + ee];
                float ay = sVw[1 * 32 + ee];
                float az = sVw[2 * 32 + ee];
                red_add_v4(base + 0 * 64 + j0,     vv[0]*ax, vv[1]*ax, vv[2]*ax, vv[3]*ax);
                red_add_v4(base + 0 * 64 + j0 + 4, vv[4]*ax, vv[5]*ax, vv[6]*ax, vv[7]*ax);
                red_add_v4(base + 1 * 64 + j0,     vv[0]*ay, vv[1]*ay, vv[2]*ay, vv[3]*ay);
                red_add_v4(base + 1 * 64 + j0 + 4, vv[4]*ay, vv[5]*ay, vv[6]*ay, vv[7]*ay);
                red_add_v4(base + 2 * 64 + j0,     vv[0]*az, vv[1]*az, vv[2]*az, vv[3]*az);
                red_add_v4(base + 2 * 64 + j0 + 4, vv[4]*az, vv[5]*az, vv[6]*az, vv[7]*az);
            }
        }
    }
}

// ---------------------------------------------------------------------------
// Phase B: per-node mean + self outer product (first NAXIS cols) -> node_desc
// ---------------------------------------------------------------------------
__global__ __launch_bounds__(256)
void node_desc_kernel(float* __restrict__ node_desc, int n_nodes)
{
    __shared__ float sa[4 * 192];
    int node0 = blockIdx.x * 4;
    long gbase = (long)node0 * 192;

    for (int i = threadIdx.x; i < 4 * 192; i += 256) {
        int node = node0 + i / 192;
        float v = 0.0f;
        if (node < n_nodes) {
            float cnt = fmaxf(g_cnt[node], 1.0f);
            v = g_sum[gbase + i] / cnt;
        }
        sa[i] = v;
    }
    __syncthreads();

    int local = threadIdx.x >> 6;
    int d     = threadIdx.x & 63;
    int node  = node0 + local;
    if (node >= n_nodes) return;

    const float* a = sa + local * 192;
    float a0 = a[0 * 64 + d];
    float a1 = a[1 * 64 + d];
    float a2 = a[2 * 64 + d];

    float o[NAXIS];
    #pragma unroll
    for (int e2 = 0; e2 < NAXIS; e2++) {
        o[e2] = a0 * a[0 * 64 + e2] + a1 * a[1 * 64 + e2] + a2 * a[2 * 64 + e2];
    }

    float4* dst = (float4*)(node_desc + (long)node * NDESC + d * NAXIS);
    dst[0] = make_float4(o[0], o[1], o[2], o[3]);
    dst[1] = make_float4(o[4], o[5], o[6], o[7]);
}

// ---------------------------------------------------------------------------
// Phase C: edge_desc[e] = node_desc[src] + node_desc[dst]
// ---------------------------------------------------------------------------
__global__ __launch_bounds__(256)
void edge_desc_kernel(const int* __restrict__ edge_index,
                      const float* __restrict__ node_desc,
                      float* __restrict__ edge_desc,
                      int n_edges)
{
    int t = threadIdx.x;
    int eidx = blockIdx.x * 2 + (t >> 7);
    if (eidx >= n_edges) return;
    int j = t & 127;

    int s = edge_index[eidx];
    int d = edge_index[n_edges + eidx];

    float4 x = ((const float4*)(node_desc + (long)s * NDESC))[j];
    float4 y = ((const float4*)(node_desc + (long)d * NDESC))[j];
    float4 rr = make_float4(x.x + y.x, x.y + y.y, x.z + y.z, x.w + y.w);
    ((float4*)(edge_desc + (long)eidx * NDESC))[j] = rr;
}

// ---------------------------------------------------------------------------
// launch
// ---------------------------------------------------------------------------
extern "C" void kernel_launch(void* const* d_in, const int* in_sizes, int n_in,
                              void* d_out, int out_size)
{
    const float* env_vec   = (const float*)d_in[0];
    const float* atom_attr = (const float*)d_in[1];
    const int*   env_index = (const int*)  d_in[2];
    const int*   edge_index= (const int*)  d_in[3];
    const float* W1 = (const float*)d_in[4];
    const float* B1 = (const float*)d_in[5];
    const float* W2 = (const float*)d_in[6];
    const float* B2 = (const float*)d_in[7];
    const float* W3 = (const float*)d_in[8];
    const float* B3 = (const float*)d_in[9];

    int n_env   = in_sizes[0] / 3;
    int n_nodes = in_sizes[1] / 4;
    int n_edges = in_sizes[3] / 2;

    float* node_desc = (float*)d_out;
    float* edge_desc = (float*)d_out + (long)n_nodes * NDESC;

    float* sum_ptr = nullptr;
    float* cnt_ptr = nullptr;
    cudaGetSymbolAddress((void**)&sum_ptr, g_sum);
    cudaGetSymbolAddress((void**)&cnt_ptr, g_cnt);

    static int smem_set = 0;
    if (!smem_set) {
        cudaFuncSetAttribute(env_mlp_scatter,
                             cudaFuncAttributeMaxDynamicSharedMemorySize, SMEM_BYTES);
        smem_set = 1;
    }

    long n_sum4 = (long)n_nodes * 48;
    long n_cnt4 = (n_nodes + 3) / 4;
    zero_all_kernel<<<2048, 256>>>((float4*)sum_ptr, n_sum4, (float4*)cnt_ptr, n_cnt4);

    int blocks = (n_env + NWARP * 32 - 1) / (NWARP * 32);
    env_mlp_scatter<<<blocks, NWARP * 32, SMEM_BYTES>>>(
        env_vec, atom_attr, env_index, W1, B1, W2, B2, W3, B3, n_env);

    node_desc_kernel<<<(n_nodes + 3) / 4, 256>>>(node_desc, n_nodes);

    edge_desc_kernel<<<(n_edges + 1) / 2, 256>>>(edge_index, node_desc, edge_desc, n_edges);
}

// round 17
// speedup vs baseline: 1.2915x; 1.1134x over previous
#include <cuda_runtime.h>
#include <cuda_bf16.h>
#include <math.h>

// Problem constants (fixed by the dataset)
#define MAX_NODES 50000
#define DHID1 32
#define DHID2 64
#define DIN   9
#define NAXIS 8
#define NDESC (DHID2 * NAXIS)   // 512

typedef unsigned long long ull_t;

// Scratch: segment-sum accumulator, axis-major: [node][axis(3)][64]
__device__ __align__(16) float g_sum[(size_t)MAX_NODES * 192];
__device__ float g_cnt[MAX_NODES];

// Dynamic shared-memory partition (float offsets) — verified round-7 layout
#define OFF_W1   0
#define OFF_B1   288
#define OFF_W2   320
#define OFF_B2   2368
#define OFF_W3   2432
#define OFF_B3   6528
#define OFF_H    6592               // 4 warps * 64*32
#define OFF_V    (OFF_H + 4*2048)   // 4 warps * 3*32
#define OFF_D    (OFF_V + 4*96)     // 4 warps * 32 ints
#define SMEM_FLOATS (OFF_D + 128)
#define SMEM_BYTES  (SMEM_FLOATS * 4)

// ---------------------------------------------------------------------------
// helpers
// ---------------------------------------------------------------------------
__device__ __forceinline__ float fast_tanh(float x) {
    // accurate (~1e-6 rel) tanh: EX2 + RCP path, clamp avoids overflow
    float xc = fminf(fmaxf(x, -9.0f), 9.0f);
    float e  = __expf(2.0f * xc);
    return __fdividef(e - 1.0f, e + 1.0f);
}

__device__ __forceinline__ void red_add_v4(float* p, float a, float b, float c, float d) {
    asm volatile("red.global.add.v4.f32 [%0], {%1, %2, %3, %4};"
                 :: "l"(p), "f"(a), "f"(b), "f"(c), "f"(d) : "memory");
}

__device__ __forceinline__ ull_t pack2(float x) {
    ull_t r;
    asm("mov.b64 %0, {%1, %1};" : "=l"(r) : "f"(x));
    return r;
}
__device__ __forceinline__ void fma2(ull_t& acc, ull_t a, ull_t b) {
    asm("fma.rn.f32x2 %0, %1, %2, %0;" : "+l"(acc) : "l"(a), "l"(b));
}
__device__ __forceinline__ float2 unpack2(ull_t v) {
    float2 f;
    asm("mov.b64 {%0, %1}, %2;" : "=f"(f.x), "=f"(f.y) : "l"(v));
    return f;
}
__device__ __forceinline__ ull_t add2(ull_t a, ull_t b) {
    ull_t r;
    asm("add.rn.f32x2 %0, %1, %2;" : "=l"(r) : "l"(a), "l"(b));
    return r;
}

// L2 eviction-priority hinted 32-byte global accesses.
// sm_103a ptxas requires .v8.b32/.v4.b64 with L2::evict_* modifiers.
__device__ __forceinline__ void ldg_evl_32B(const void* p, ull_t& a, ull_t& b,
                                            ull_t& c, ull_t& d) {
    asm volatile("ld.global.nc.L2::evict_last.v4.b64 {%0, %1, %2, %3}, [%4];"
                 : "=l"(a), "=l"(b), "=l"(c), "=l"(d) : "l"(p));
}
__device__ __forceinline__ void stg_evf_32B(void* p, ull_t a, ull_t b,
                                            ull_t c, ull_t d) {
    asm volatile("st.global.L2::evict_first.v4.b64 [%0], {%1, %2, %3, %4};"
                 :: "l"(p), "l"(a), "l"(b), "l"(c), "l"(d) : "memory");
}

// ---------------------------------------------------------------------------
// zero scratch
// ---------------------------------------------------------------------------
__global__ void zero_all_kernel(float4* sum4, long n4, float4* cnt4, long c4) {
    long i = (long)blockIdx.x * blockDim.x + threadIdx.x;
    long stride = (long)gridDim.x * blockDim.x;
    float4 z = make_float4(0.f, 0.f, 0.f, 0.f);
    for (long k = i; k < n4; k += stride) sum4[k] = z;
    for (long k = i; k < c4; k += stride) cnt4[k] = z;
}

// ---------------------------------------------------------------------------
// Phase A: per-env MLP (verified round-7 structure, 626 us).
// Layers 1-2 per-thread (packed FFMA2); layer 3 warp-cooperative
// 32env x 64out tile over smem-staged h2.
// ---------------------------------------------------------------------------
__global__ __launch_bounds__(128)
void env_mlp_scatter(const float* __restrict__ env_vec,
                     const float* __restrict__ atom_attr,
                     const int*   __restrict__ env_index,
                     const float* __restrict__ W1, const float* __restrict__ B1,
                     const float* __restrict__ W2, const float* __restrict__ B2,
                     const float* __restrict__ W3, const float* __restrict__ B3,
                     int n_env)
{
    extern __shared__ __align__(16) float sm[];
    float* sW1 = sm + OFF_W1;
    float* sB1 = sm + OFF_B1;
    float* sW2 = sm + OFF_W2;
    float* sB2 = sm + OFF_B2;
    float* sW3 = sm + OFF_W3;
    float* sB3 = sm + OFF_B3;

    for (int i = threadIdx.x; i < DIN * DHID1;   i += blockDim.x) sW1[i] = W1[i];
    for (int i = threadIdx.x; i < DHID1 * DHID2; i += blockDim.x) sW2[i] = W2[i];
    for (int i = threadIdx.x; i < DHID2 * DHID2; i += blockDim.x) sW3[i] = W3[i];
    if (threadIdx.x < DHID1) sB1[threadIdx.x] = B1[threadIdx.x];
    if (threadIdx.x < DHID2) { sB2[threadIdx.x] = B2[threadIdx.x]; sB3[threadIdx.x] = B3[threadIdx.x]; }
    __syncthreads();

    int warp = threadIdx.x >> 5;
    int lane = threadIdx.x & 31;
    float* sHw = sm + OFF_H + warp * 2048;          // [64 k][32 env]
    float* sVw = sm + OFF_V + warp * 96;            // [3][32]
    int*   sDw = (int*)(sm + OFF_D) + warp * 32;    // [32]

    int warp_env_base = (blockIdx.x * 4 + warp) * 32;
    int e_mine = warp_env_base + lane;
    int e = min(e_mine, n_env - 1);

    // ---- per-env input ----
    float vx = env_vec[3 * e + 0];
    float vy = env_vec[3 * e + 1];
    float vz = env_vec[3 * e + 2];
    float r  = sqrtf(vx * vx + vy * vy + vz * vz);

    float snorm;
    if (r < 3.0f) {
        snorm = 1.0f / r;
    } else if (r < 6.0f) {
        float x = (r - 6.0f) * (-1.0f / 3.0f);
        snorm = (1.0f / r) * (x * x * x * (10.0f + x * (-15.0f + 6.0f * x)) + 1.0f);
    } else {
        snorm = 0.0f;
    }

    int src = env_index[e];
    int dst = env_index[n_env + e];
    float4 as = *(const float4*)(atom_attr + 4 * src);
    float4 ad = *(const float4*)(atom_attr + 4 * dst);
    float in[DIN] = {snorm, as.x, as.y, as.z, as.w, ad.x, ad.y, ad.z, ad.w};

    // ---- layer 1: [9] -> [32] ----
    float h1[DHID1];
    {
        ull_t acc[16];
        #pragma unroll
        for (int j = 0; j < 16; j++) acc[j] = *(const ull_t*)(sB1 + 2 * j);
        #pragma unroll
        for (int k = 0; k < DIN; k++) {
            ull_t x2 = pack2(in[k]);
            #pragma unroll
            for (int jj = 0; jj < 8; jj++) {
                ulonglong2 w = *(const ulonglong2*)(sW1 + k * DHID1 + jj * 4);
                fma2(acc[2 * jj + 0], x2, w.x);
                fma2(acc[2 * jj + 1], x2, w.y);
            }
        }
        #pragma unroll
        for (int j = 0; j < 16; j++) {
            float2 t = unpack2(acc[j]);
            h1[2 * j + 0] = fast_tanh(t.x);
            h1[2 * j + 1] = fast_tanh(t.y);
        }
    }

    // ---- layer 2: [32] -> [64], j-chunks of 32; stage h2 straight to smem ----
    #pragma unroll
    for (int c = 0; c < DHID2; c += 32) {
        ull_t acc[16];
        #pragma unroll
        for (int j = 0; j < 16; j++) acc[j] = *(const ull_t*)(sB2 + c + 2 * j);
        #pragma unroll
        for (int k = 0; k < DHID1; k++) {
            ull_t x2 = pack2(h1[k]);
            #pragma unroll
            for (int jj = 0; jj < 8; jj++) {
                ulonglong2 w = *(const ulonglong2*)(sW2 + k * DHID2 + c + jj * 4);
                fma2(acc[2 * jj + 0], x2, w.x);
                fma2(acc[2 * jj + 1], x2, w.y);
            }
        }
        #pragma unroll
        for (int j = 0; j < 16; j++) {
            float2 t = unpack2(acc[j]);
            sHw[(c + 2 * j + 0) * 32 + lane] = fast_tanh(t.x);
            sHw[(c + 2 * j + 1) * 32 + lane] = fast_tanh(t.y);
        }
    }

    // stage v / dst; per-env count
    sVw[0 * 32 + lane] = vx;
    sVw[1 * 32 + lane] = vy;
    sVw[2 * 32 + lane] = vz;
    sDw[lane] = dst;
    if (e_mine < n_env) atomicAdd(g_cnt + dst, 1.0f);
    __syncwarp();

    // ---- layer 3: warp-tiled. lane = eg*8 + og: envs [8eg,8eg+8), outs [8og,8og+8) ----
    int eg = lane >> 3;
    int og = lane & 7;
    int j0 = og * 8;
    int ebase = eg * 8;

    ull_t acc[8][4];   // [out j][env pair]
    #pragma unroll
    for (int j = 0; j < 8; j++) {
        ull_t b = pack2(sB3[j0 + j]);
        acc[j][0] = b; acc[j][1] = b; acc[j][2] = b; acc[j][3] = b;
    }

    #pragma unroll 8
    for (int k = 0; k < DHID2; k++) {
        ulonglong2 A0 = *(const ulonglong2*)(sHw + k * 32 + ebase);      // envs 0..3
        ulonglong2 A1 = *(const ulonglong2*)(sHw + k * 32 + ebase + 4);  // envs 4..7
        float4 w0 = *(const float4*)(sW3 + k * DHID2 + j0);
        float4 w1 = *(const float4*)(sW3 + k * DHID2 + j0 + 4);
        ull_t wj[8] = {pack2(w0.x), pack2(w0.y), pack2(w0.z), pack2(w0.w),
                       pack2(w1.x), pack2(w1.y), pack2(w1.z), pack2(w1.w)};
        #pragma unroll
        for (int j = 0; j < 8; j++) {
            fma2(acc[j][0], A0.x, wj[j]);
            fma2(acc[j][1], A0.y, wj[j]);
            fma2(acc[j][2], A1.x, wj[j]);
            fma2(acc[j][3], A1.y, wj[j]);
        }
    }

    // residuals for this tile: h2[j0+j][ebase..ebase+7]
    ull_t resu[8][4];
    #pragma unroll
    for (int j = 0; j < 8; j++) {
        ulonglong2 R0 = *(const ulonglong2*)(sHw + (j0 + j) * 32 + ebase);
        ulonglong2 R1 = *(const ulonglong2*)(sHw + (j0 + j) * 32 + ebase + 4);
        resu[j][0] = R0.x; resu[j][1] = R0.y; resu[j][2] = R1.x; resu[j][3] = R1.y;
    }

    // epilogue: tanh + residual, multiply by env vector, scatter (RED v4)
    #pragma unroll
    for (int ep = 0; ep < 4; ep++) {
        float v0[8], v1[8];
        #pragma unroll
        for (int j = 0; j < 8; j++) {
            float2 f = unpack2(acc[j][ep]);
            float2 rr = unpack2(resu[j][ep]);
            v0[j] = fast_tanh(f.x) + rr.x;
            v1[j] = fast_tanh(f.y) + rr.y;
        }
        #pragma unroll
        for (int half = 0; half < 2; half++) {
            int ee = ebase + 2 * ep + half;
            if (warp_env_base + ee < n_env) {
                const float* vv = half ? v1 : v0;
                float* base = g_sum + (long)sDw[ee] * 192;
                float ax = sVw[0 * 32 + ee];
                float ay = sVw[1 * 32 + ee];
                float az = sVw[2 * 32 + ee];
                red_add_v4(base + 0 * 64 + j0,     vv[0]*ax, vv[1]*ax, vv[2]*ax, vv[3]*ax);
                red_add_v4(base + 0 * 64 + j0 + 4, vv[4]*ax, vv[5]*ax, vv[6]*ax, vv[7]*ax);
                red_add_v4(base + 1 * 64 + j0,     vv[0]*ay, vv[1]*ay, vv[2]*ay, vv[3]*ay);
                red_add_v4(base + 1 * 64 + j0 + 4, vv[4]*ay, vv[5]*ay, vv[6]*ay, vv[7]*ay);
                red_add_v4(base + 2 * 64 + j0,     vv[0]*az, vv[1]*az, vv[2]*az, vv[3]*az);
                red_add_v4(base + 2 * 64 + j0 + 4, vv[4]*az, vv[5]*az, vv[6]*az, vv[7]*az);
            }
        }
    }
}

// ---------------------------------------------------------------------------
// Phase B: per-node mean + self outer product (first NAXIS cols) -> node_desc
// ---------------------------------------------------------------------------
__global__ __launch_bounds__(256)
void node_desc_kernel(float* __restrict__ node_desc, int n_nodes)
{
    __shared__ float sa[4 * 192];
    int node0 = blockIdx.x * 4;
    long gbase = (long)node0 * 192;

    for (int i = threadIdx.x; i < 4 * 192; i += 256) {
        int node = node0 + i / 192;
        float v = 0.0f;
        if (node < n_nodes) {
            float cnt = fmaxf(g_cnt[node], 1.0f);
            v = g_sum[gbase + i] / cnt;
        }
        sa[i] = v;
    }
    __syncthreads();

    int local = threadIdx.x >> 6;
    int d     = threadIdx.x & 63;
    int node  = node0 + local;
    if (node >= n_nodes) return;

    const float* a = sa + local * 192;
    float a0 = a[0 * 64 + d];
    float a1 = a[1 * 64 + d];
    float a2 = a[2 * 64 + d];

    float o[NAXIS];
    #pragma unroll
    for (int e2 = 0; e2 < NAXIS; e2++) {
        o[e2] = a0 * a[0 * 64 + e2] + a1 * a[1 * 64 + e2] + a2 * a[2 * 64 + e2];
    }

    float4* dst = (float4*)(node_desc + (long)node * NDESC + d * NAXIS);
    dst[0] = make_float4(o[0], o[1], o[2], o[3]);
    dst[1] = make_float4(o[4], o[5], o[6], o[7]);
}

// ---------------------------------------------------------------------------
// Phase C: edge_desc[e] = node_desc[src] + node_desc[dst].
// 32-byte accesses (64 threads per 512-float row, 4 edges per block).
// node_desc reads pinned L2::evict_last; edge stream written L2::evict_first.
// ---------------------------------------------------------------------------
__global__ __launch_bounds__(256)
void edge_desc_kernel(const int* __restrict__ edge_index,
                      const float* __restrict__ node_desc,
                      float* __restrict__ edge_desc,
                      int n_edges)
{
    int t = threadIdx.x;
    int eidx = blockIdx.x * 4 + (t >> 6);   // 4 edges per block, 64 threads each
    if (eidx >= n_edges) return;
    int j = t & 63;                         // 32-byte chunk index (64 per row)

    int s = edge_index[eidx];
    int d = edge_index[n_edges + eidx];

    const char* ps = (const char*)(node_desc + (long)s * NDESC) + j * 32;
    const char* pd = (const char*)(node_desc + (long)d * NDESC) + j * 32;
    char*       po = (char*)(edge_desc + (long)eidx * NDESC) + j * 32;

    ull_t xa, xb, xc, xd, ya, yb, yc, yd;
    ldg_evl_32B(ps, xa, xb, xc, xd);
    ldg_evl_32B(pd, ya, yb, yc, yd);
    stg_evf_32B(po, add2(xa, ya), add2(xb, yb), add2(xc, yc), add2(xd, yd));
}

// ---------------------------------------------------------------------------
// launch
// ---------------------------------------------------------------------------
extern "C" void kernel_launch(void* const* d_in, const int* in_sizes, int n_in,
                              void* d_out, int out_size)
{
    const float* env_vec   = (const float*)d_in[0];
    const float* atom_attr = (const float*)d_in[1];
    const int*   env_index = (const int*)  d_in[2];
    const int*   edge_index= (const int*)  d_in[3];
    const float* W1 = (const float*)d_in[4];
    const float* B1 = (const float*)d_in[5];
    const float* W2 = (const float*)d_in[6];
    const float* B2 = (const float*)d_in[7];
    const float* W3 = (const float*)d_in[8];
    const float* B3 = (const float*)d_in[9];

    int n_env   = in_sizes[0] / 3;
    int n_nodes = in_sizes[1] / 4;
    int n_edges = in_sizes[3] / 2;

    float* node_desc = (float*)d_out;
    float* edge_desc = (float*)d_out + (long)n_nodes * NDESC;

    float* sum_ptr = nullptr;
    float* cnt_ptr = nullptr;
    cudaGetSymbolAddress((void**)&sum_ptr, g_sum);
    cudaGetSymbolAddress((void**)&cnt_ptr, g_cnt);

    static int smem_set = 0;
    if (!smem_set) {
        cudaFuncSetAttribute(env_mlp_scatter,
                             cudaFuncAttributeMaxDynamicSharedMemorySize, SMEM_BYTES);
        smem_set = 1;
    }

    long n_sum4 = (long)n_nodes * 48;
    long n_cnt4 = (n_nodes + 3) / 4;
    zero_all_kernel<<<2048, 256>>>((float4*)sum_ptr, n_sum4, (float4*)cnt_ptr, n_cnt4);

    int blocks = (n_env + 127) / 128;
    env_mlp_scatter<<<blocks, 128, SMEM_BYTES>>>(
        env_vec, atom_attr, env_index, W1, B1, W2, B2, W3, B3, n_env);

    node_desc_kernel<<<(n_nodes + 3) / 4, 256>>>(node_desc, n_nodes);

    edge_desc_kernel<<<(n_edges + 3) / 4, 256>>>(edge_index, node_desc, edge_desc, n_edges);
}